// round 9
// baseline (speedup 1.0000x reference)
#include <cuda_runtime.h>

#define BB 16
#define HH 512
#define WW 512
#define HW (HH*WW)
#define NN (BB*HW)
#define WPR 16                 // words per row
#define WPI (HH*WPR)           // words per image = 8192
#define TOT (BB*WPI)           // total words = 131072

#define GRID 592               // 4 blocks/SM x 148 SMs -> all co-resident
#define TPB  256

// bit j of word (b,y,w) = pixel x = w*32 + j ; pixel index = 32*wordIdx + j

__device__ unsigned g_F[TOT];
__device__ unsigned g_G[TOT];
__device__ unsigned g_H[TOT];
// double-buffered union-find state: CCL1 & CCL3 use buf 0, hole-CCL uses buf 1
__device__ int g_L0[NN];
__device__ int g_S0[NN];
__device__ int g_L1[NN];
__device__ int g_S1[NN];
__device__ int g_nc[BB];
// software grid barrier
__device__ volatile unsigned g_gen;
__device__ unsigned g_count;

// ---------------- grid barrier (all blocks resident by construction) ----------------
__device__ __forceinline__ void gsync() {
    __syncthreads();
    if (threadIdx.x == 0) {
        __threadfence();
        unsigned gen = g_gen;
        if (atomicAdd(&g_count, 1u) == gridDim.x - 1u) {
            g_count = 0u;
            __threadfence();
            g_gen = gen + 1u;               // release
        } else {
            while (g_gen == gen) { }        // spin
            __threadfence();                // acquire
        }
    }
    __syncthreads();
}

// ---------------- bit helpers ----------------
__device__ __forceinline__ int runlen(unsigned m, int j) {
    unsigned nt = ~(m >> j);
    return nt ? (__ffs(nt) - 1) : (32 - j);
}
__device__ __forceinline__ unsigned runmask(int j, int e) {
    return (e >= 32) ? 0xffffffffu : (((1u << e) - 1u) << j);
}
__device__ __forceinline__ int rstart(unsigned m, int j) {
    unsigned zeros = (~m) & (j ? ((1u << j) - 1u) : 0u);
    return zeros ? (32 - __clz(zeros)) : 0;
}
__device__ __forceinline__ void init_runs(unsigned m, int t, int* L, int* S) {
    int base = t * 32;
    while (m) {
        int j = __ffs(m) - 1;
        int e = runlen(m, j);
        L[base + j] = base + j;
        S[base + j] = 0;
        m &= ~runmask(j, e);
    }
}

// ---------------- union-find ----------------
__device__ __forceinline__ int findroot_h(int* L, int i) {
    volatile int* V = L;
    int p;
    while ((p = V[i]) != i) {
        int gp = V[p];
        if (gp == p) return p;
        atomicCAS(&L[i], p, gp);     // CAS path-halving: safe vs concurrent atomicMin
        i = gp;
    }
    return i;
}
__device__ void unite(int* L, int a, int b) {
    while (true) {
        a = findroot_h(L, a);
        b = findroot_h(L, b);
        if (a == b) return;
        if (a > b) { int t = a; a = b; b = t; }
        int old = atomicMin(&L[b], a);
        if (old == b) return;
        b = old;
    }
}
__device__ __forceinline__ int root_at(const int* L, int i) {
    int r = L[i];
    while (L[r] != r) r = L[r];
    return r;
}

// ---------------- phase bodies (grid-stride, no early return) ----------------
__device__ void d_pack(const float* __restrict__ in, int gtid, int gsz) {
    for (int i = gtid; i < NN; i += gsz) {
        unsigned b = __ballot_sync(0xffffffffu, in[i] > 0.0f);
        if ((i & 31) == 0) {
            int t = i >> 5;
            g_F[t] = b;
            if ((t & (WPI - 1)) == 0) g_nc[t >> 13] = 0;
            init_runs(b, t, g_L0, g_S0);
        }
    }
}

template<bool INV>
__device__ void d_merge(const unsigned* __restrict__ F, int* L, int gtid, int gsz) {
    for (int t = gtid; t < TOT; t += gsz) {
        unsigned cur = F[t]; if (INV) cur = ~cur;
        if (!cur) continue;
        int w = t & 15, y = (t >> 4) & 511;
        int base = t * 32;
        if (w > 0 && (cur & 1u)) {
            unsigned left = F[t - 1]; if (INV) left = ~left;
            if (left >> 31) unite(L, base, (t - 1) * 32 + rstart(left, 31));
        }
        if (y > 0) {
            unsigned up = F[t - WPR]; if (INV) up = ~up;
            unsigned ov = cur & up;
            unsigned starts = ov & ~(ov << 1);
            while (starts) {
                int j = __ffs(starts) - 1;
                starts &= starts - 1;
                unite(L, base + rstart(cur, j), base - WW + rstart(up, j));
            }
        }
    }
}

template<bool INV, bool NC>
__device__ void d_count(const unsigned* __restrict__ F, int* L, int* S, int gtid, int gsz) {
    for (int t = gtid; t < TOT; t += gsz) {
        unsigned m = F[t]; if (INV) m = ~m;
        if (!m) continue;
        int base = t * 32, b = t >> 13;
        while (m) {
            int j = __ffs(m) - 1;
            int e = runlen(m, j);
            int i = base + j;
            int r = findroot_h(L, i);
            L[i] = r;                       // owner-only compression write
            atomicAdd(&S[r], e);
            if (NC && r == i) atomicAdd(&g_nc[b], 1);
            m &= ~runmask(j, e);
        }
    }
}

// filter CCL1 (guarded) + init hole-CCL labels (buf 1) on the inverted result
__device__ void d_filter_init(unsigned* F, int min_size, int gtid, int gsz) {
    for (int t = gtid; t < TOT; t += gsz) {
        unsigned m = F[t];
        unsigned keep = m;
        if (m && g_nc[t >> 13] > 1) {
            int base = t * 32;
            unsigned mm = m;
            while (mm) {
                int j = __ffs(mm) - 1;
                int e = runlen(mm, j);
                if (g_S0[root_at(g_L0, base + j)] < min_size) keep &= ~runmask(j, e);
                mm &= ~runmask(j, e);
            }
            if (keep != m) F[t] = keep;
        }
        init_runs(~keep, t, g_L1, g_S1);
    }
}

__device__ void d_filter(unsigned* F, int min_size, int gtid, int gsz) {
    for (int t = gtid; t < TOT; t += gsz) {
        unsigned m = F[t];
        if (!m) continue;
        if (g_nc[t >> 13] <= 1) continue;
        int base = t * 32;
        unsigned keep = m, mm = m;
        while (mm) {
            int j = __ffs(mm) - 1;
            int e = runlen(mm, j);
            if (g_S0[root_at(g_L0, base + j)] < min_size) keep &= ~runmask(j, e);
            mm &= ~runmask(j, e);
        }
        if (keep != m) F[t] = keep;
    }
}

__device__ void d_fill(unsigned* F, int thresh, int gtid, int gsz) {
    for (int t = gtid; t < TOT; t += gsz) {
        unsigned m = ~F[t];
        if (!m) continue;
        int base = t * 32;
        unsigned add = 0, mm = m;
        while (mm) {
            int j = __ffs(mm) - 1;
            int e = runlen(mm, j);
            if (g_S1[root_at(g_L1, base + j)] < thresh) add |= runmask(j, e);
            mm &= ~runmask(j, e);
        }
        if (add) F[t] |= add;
    }
}

// ---------------- morphology ----------------
__host__ __device__ constexpr int hwidth(int R, int dy) {
    int w = 0;
    while ((w + 1) * (w + 1) + dy * dy <= R * R) ++w;
    return w;
}

template<int R, bool ER, bool INIT>
__device__ void d_morph(const unsigned* __restrict__ in, unsigned* __restrict__ out,
                        int gtid, int gsz) {
    for (int t = gtid; t < TOT; t += gsz) {
        int w = t & 15, y = (t >> 4) & 511, b = t >> 13;
        const unsigned* img = in + b * WPI;
        const unsigned border = ER ? 0xffffffffu : 0u;
        unsigned acc = border;
#pragma unroll
        for (int dy = -R; dy <= R; dy++) {
            int yy = y + dy;
            unsigned c, l, r;
            if (yy < 0 || yy >= HH) { c = border; l = border; r = border; }
            else {
                c = img[yy * WPR + w];
                l = (w > 0)  ? img[yy * WPR + w - 1] : border;
                r = (w < 15) ? img[yy * WPR + w + 1] : border;
            }
            unsigned rowacc = c;
            const int wd = hwidth(R, dy);
#pragma unroll
            for (int s = 1; s <= wd; s++) {
                unsigned rs = __funnelshift_r(c, r, s);
                unsigned ls = __funnelshift_l(l, c, s);
                if (ER) rowacc &= rs & ls; else rowacc |= rs | ls;
            }
            if (ER) acc &= rowacc; else acc |= rowacc;
        }
        out[t] = acc;
        if (INIT) {                     // prep CCL3 (buf 0)
            if ((t & (WPI - 1)) == 0) g_nc[t >> 13] = 0;
            init_runs(acc, t, g_L0, g_S0);
        }
    }
}

// final dilate(disk1) + unpack to float
__device__ void d_out(const unsigned* __restrict__ in, float* __restrict__ out,
                      int gtid, int gsz) {
    for (int g = gtid; g < NN; g += gsz) {
        int lane = g & 31;
        int t = g >> 5;
        int w = t & 15, y = (t >> 4) & 511, b = t >> 13;
        const unsigned* img = in + b * WPI;
        unsigned c = img[y * WPR + w];
        unsigned l = (w > 0)   ? img[y * WPR + w - 1] : 0u;
        unsigned r = (w < 15)  ? img[y * WPR + w + 1] : 0u;
        unsigned u = (y > 0)   ? img[(y - 1) * WPR + w] : 0u;
        unsigned d = (y < 511) ? img[(y + 1) * WPR + w] : 0u;
        unsigned res = c | u | d | __funnelshift_r(c, r, 1) | __funnelshift_l(l, c, 1);
        out[b * HW + y * WW + w * 32 + lane] = (float)((res >> lane) & 1u);
    }
}

// ---------------- the whole pipeline: ONE kernel, 13 grid barriers ----------------
__global__ void __launch_bounds__(TPB, 4) k_all(const float* __restrict__ in,
                                                float* __restrict__ out) {
    int gtid = blockIdx.x * blockDim.x + threadIdx.x;
    int gsz = gridDim.x * blockDim.x;

    d_pack(in, gtid, gsz);                                  gsync();
    // remove_small_objects(fg, 2000, guarded)
    d_merge<false>(g_F, g_L0, gtid, gsz);                   gsync();
    d_count<false, true>(g_F, g_L0, g_S0, gtid, gsz);       gsync();
    d_filter_init(g_F, 2000, gtid, gsz);                    gsync();
    // fill small holes (< 301 px)
    d_merge<true>(g_F, g_L1, gtid, gsz);                    gsync();
    d_count<true, false>(g_F, g_L1, g_S1, gtid, gsz);       gsync();
    d_fill(g_F, 301, gtid, gsz);                            gsync();
    // erode disk(2), then opening disk(5): erode, dilate(+init CCL3)
    d_morph<2, true , false>(g_F, g_G, gtid, gsz);          gsync();
    d_morph<5, true , false>(g_G, g_H, gtid, gsz);          gsync();
    d_morph<5, false, true >(g_H, g_G, gtid, gsz);          gsync();
    // remove_small_objects(fg, 2000, guarded)
    d_merge<false>(g_G, g_L0, gtid, gsz);                   gsync();
    d_count<false, true>(g_G, g_L0, g_S0, gtid, gsz);       gsync();
    d_filter(g_G, 2000, gtid, gsz);                         gsync();
    // dilate(disk1) -> float out
    d_out(g_G, out, gtid, gsz);
}

// ---------------- launch ----------------
extern "C" void kernel_launch(void* const* d_in, const int* in_sizes, int n_in,
                              void* d_out, int out_size) {
    (void)in_sizes; (void)n_in; (void)out_size;
    k_all<<<GRID, TPB>>>((const float*)d_in[0], (float*)d_out);
}